// round 12
// baseline (speedup 1.0000x reference)
#include <cuda_runtime.h>

typedef unsigned int u32;
typedef unsigned long long u64;

#define BATCH  8
#define NPTS   100000
#define NCLS   10
#define KTOP   1000
#define NROWS  (BATCH * NCLS)      // 80
#define NFLAT  (NCLS * KTOP)       // 10000
#define ORD_NEG1 0x407FFFFFu       // f2ord(-1.0f)
#define TI     512

// dynamic smem layout (phase A select, phase B NMS overlays whist/big region)
#define OFF_WHIST 0                // u32[32*256]  32768
#define OFF_BIG   32768            // u64[1024]     8192
#define OFF_TIE   40960            // u64[256]      2048
#define OFF_FIN   43008            // u64[1024]     8192
#define SMEM_SZ   51200            // > 48KB: needs cudaFuncSetAttribute!

// ---------------- static device scratch -------------------------------------
__device__ u32 d_ord[NROWS * NPTS];       // 32 MB ordered score bits
__device__ u64 d_k1 [NROWS * KTOP];       // stage-1 sorted keys
__device__ u64 d_k2 [BATCH * NFLAT];      // stage-2 candidate keys

// ---------------- helpers ----------------------------------------------------
__device__ __forceinline__ u32 f2ord(float f) {
    u32 b = __float_as_uint(f);
    return b ^ ((b & 0x80000000u) ? 0xFFFFFFFFu : 0x80000000u);
}
__device__ __forceinline__ float ord2f(u32 u) {
    u32 b = u ^ ((u & 0x80000000u) ? 0x80000000u : 0xFFFFFFFFu);
    return __uint_as_float(b);
}

// Decision identical to RN(inter/uni) > t (margins dwarf 2^-24 rounding).
__device__ __forceinline__ bool iou_gt(float4 a, float areaA, float4 c, float areaC,
                                       float t, float tLo, float tHi) {
    float ih = fmaxf(fminf(a.z, c.z) - fmaxf(a.x, c.x), 0.0f);
    float iw = fmaxf(fminf(a.w, c.w) - fmaxf(a.y, c.y), 0.0f);
    float inter = ih * iw;
    float uni = fmaxf(areaA + areaC - inter, 1e-8f);
    if (inter > tHi * uni) return true;
    if (inter >= tLo * uni) return inter / uni > t;
    return false;
}

__device__ void bitonic_desc(u64* s, int n) {
    for (int k = 2; k <= n; k <<= 1) {
        for (int j = k >> 1; j > 0; j >>= 1) {
            __syncthreads();
            for (int i = threadIdx.x; i < n; i += blockDim.x) {
                int ixj = i ^ j;
                if (ixj > i) {
                    u64 a = s[i], bb = s[ixj];
                    if ((a < bb) == ((i & k) == 0)) { s[i] = bb; s[ixj] = a; }
                }
            }
        }
    }
    __syncthreads();
}

// Select highest 8-bit bin with count(>bin) < K <= count(>=bin) from the
// 32-warp privatized histogram. 1024 threads, 3 barriers.
__device__ void sel8(const u32* whist, u32* swarp, int K, u32* s_sel, int* s_krem) {
    int tid = threadIdx.x, lane = tid & 31, wid = tid >> 5;
    u32 cnt = 0;
    if (tid < 256) {
        #pragma unroll
        for (int w = 0; w < 32; w++) cnt += whist[w * 256 + tid];
    }
    u32 v = cnt;
    #pragma unroll
    for (int off = 1; off < 32; off <<= 1) {
        u32 n = __shfl_down_sync(0xFFFFFFFFu, v, off);
        if (lane + off < 32) v += n;
    }
    if (tid < 256 && lane == 0) swarp[wid] = v;
    __syncthreads();
    if (tid < 32) {
        u32 w8 = (lane < 8) ? swarp[lane] : 0u;
        #pragma unroll
        for (int off = 1; off < 8; off <<= 1) {
            u32 n = __shfl_down_sync(0xFFFFFFFFu, w8, off);
            if (lane + off < 8) w8 += n;
        }
        if (lane < 8) swarp[lane] = w8;
    }
    __syncthreads();
    if (tid < 256) {
        u32 S = v + ((wid < 7) ? swarp[wid + 1] : 0u);
        u32 above = S - cnt;
        if (above < (u32)K && S >= (u32)K) { *s_sel = (u32)tid; *s_krem = K - (int)above; }
    }
    __syncthreads();
}

// Privatized histogram add: no atomics. Leaders (per distinct digit) of each
// warp write distinct addresses in their own 256-bin row — lockstep-safe.
__device__ __forceinline__ void whist_add(u32* whist, bool part, u32 dgt,
                                          int lane, int wid) {
    u32 act = __ballot_sync(0xFFFFFFFFu, part);
    if (part) {
        u32 peers = __match_any_sync(act, dgt);
        if (lane == __ffs(peers) - 1)
            whist[wid * 256 + dgt] += (u32)__popc(peers);
    }
}

// Warp-aggregated append: one atomicAdd per warp per condition.
__device__ __forceinline__ void wagg_append(u64* buf, int cap, int* ctr,
                                            bool cond, u64 val, int lane) {
    u32 m = __ballot_sync(0xFFFFFFFFu, cond);
    if (m) {
        int ldr = __ffs(m) - 1;
        int base = 0;
        if (lane == ldr) base = atomicAdd(ctr, __popc(m));
        base = __shfl_sync(0xFFFFFFFFu, base, ldr);
        if (cond) {
            int pos = base + __popc(m & ((1u << lane) - 1u));
            if (pos < cap) buf[pos] = val;
        }
    }
}

// ---------------- thread-owns-box blocked greedy NMS -------------------------
struct NmsSh {
    float4 box[1024];
    float  area[1024];
    u64    mat[64];
    u32    cand[2];
    u64    alive;
    int    aliveList[64];
    int    aliveCnt;
};

__device__ bool nms_greedy(NmsSh* ns, float4 my, float myarea, bool myvalid,
                           float thresh, int tid) {
    const float tLo = thresh * 0.999f, tHi = thresh * 1.001f;
    bool supp = false, kept = false;
    int myblk = tid >> 6;
    int lane = tid & 31;
    for (int blk = 0; blk < 16; blk++) {
        if ((tid >> 6) == blk) {                 // warp-uniform (2 warps)
            u32 bal = __ballot_sync(0xFFFFFFFFu, myvalid && !supp);
            if (lane == 0) ns->cand[(tid >> 5) & 1] = bal;
        }
        __syncthreads();
        u64 cand = ((u64)ns->cand[1] << 32) | (u64)ns->cand[0];
        int base = blk << 6;

        {   // intra-block 64x64 over candidate pairs only
            int i = tid >> 4;
            u64 bits = 0ULL;
            if ((cand >> i) & 1ULL) {
                float4 a = ns->box[base + i];
                float areaA = ns->area[base + i];
                int j0 = (tid & 15) << 2;
                #pragma unroll
                for (int q = 0; q < 4; q++) {
                    int j = j0 + q;
                    if (j > i && ((cand >> j) & 1ULL)) {
                        if (iou_gt(a, areaA, ns->box[base + j], ns->area[base + j],
                                   thresh, tLo, tHi))
                            bits |= 1ULL << j;
                    }
                }
            }
            #pragma unroll
            for (int off = 8; off; off >>= 1)
                bits |= __shfl_xor_sync(0xFFFFFFFFu, bits, off);
            if ((tid & 15) == 0) ns->mat[tid >> 4] = bits;
        }
        __syncthreads();

        if (tid == 0) {                          // serial resolve + list expand
            u64 suppB = 0ULL, aliveB = 0ULL;
            for (int q0 = 0; q0 < 64; q0 += 8) {
                u64 dw[8];
                #pragma unroll
                for (int r = 0; r < 8; r++) dw[r] = ns->mat[q0 + r];
                #pragma unroll
                for (int r = 0; r < 8; r++) {
                    int q = q0 + r;
                    if (((cand >> q) & 1ULL) && !((suppB >> q) & 1ULL)) {
                        aliveB |= 1ULL << q;
                        suppB |= dw[r];
                    }
                }
            }
            ns->alive = aliveB;
            int n = 0;
            u64 tmp = aliveB;
            while (tmp) {
                int q = __ffsll(tmp) - 1;
                tmp &= tmp - 1;
                ns->aliveList[n++] = base + q;
            }
            ns->aliveCnt = n;
        }
        __syncthreads();
        u64 aliveM = ns->alive;

        if (myblk == blk) {
            kept = myvalid && ((aliveM >> (tid & 63)) & 1ULL);
            supp = !kept;
        } else if (myblk > blk && myvalid && !supp) {
            int nA = ns->aliveCnt;
            bool s = false;
            for (int k0 = 0; k0 < nA && !s; k0 += 8) {   // 8 indep tests in flight
                int kmax = nA - k0;
                #pragma unroll
                for (int q = 0; q < 8; q++) {
                    if (q < kmax) {
                        int ii = ns->aliveList[k0 + q];
                        s |= iou_gt(ns->box[ii], ns->area[ii], my, myarea,
                                    thresh, tLo, tHi);
                    }
                }
            }
            supp = s;
        }
    }
    return kept;
}

// ---------------- K0: profiling-slot shim ------------------------------------
__global__ void k_nop() {}

// ---------------- K1: mask + transpose to per-(b,c) rows --------------------
__global__ void k_transpose(const float* __restrict__ cls) {
    __shared__ u32 tile[TI * NCLS];
    int b  = blockIdx.y;
    int i0 = blockIdx.x * TI;
    int cnt = min(TI, NPTS - i0);
    const float* src = cls + ((size_t)b * NPTS + i0) * NCLS;
    for (int t = threadIdx.x; t < cnt * NCLS; t += blockDim.x) {
        float s = src[t];
        s = (s >= 0.05f) ? s : -1.0f;
        tile[t] = f2ord(s);
    }
    __syncthreads();
    for (int c = 0; c < NCLS; ++c) {
        u32* dst = d_ord + (size_t)(b * NCLS + c) * NPTS + i0;
        for (int r = threadIdx.x; r < cnt; r += blockDim.x)
            dst[r] = tile[r * NCLS + c];
    }
}

// ---------------- K2: fused stage-1 select (3x8-bit, privatized) + NMS -------
__global__ void __launch_bounds__(1024) k_s1(const float4* __restrict__ boxes) {
    extern __shared__ char sm[];
    u32* whist = (u32*)(sm + OFF_WHIST);
    u64* sbig  = (u64*)(sm + OFF_BIG);
    u64* stie  = (u64*)(sm + OFF_TIE);
    u64* sfin  = (u64*)(sm + OFF_FIN);
    NmsSh* ns  = (NmsSh*)sm;
    __shared__ u32 swarp[32];
    __shared__ u32 s_sel;
    __shared__ int s_krem, s_ng, s_nt;

    int row = blockIdx.x;
    int b = row / NCLS, c = row % NCLS;
    const u32* ord = d_ord + (size_t)row * NPTS;
    int tid = threadIdx.x, lane = tid & 31, wid = tid >> 5;
    const int nIter = (NPTS + 1023) / 1024;

    if (tid == 0) { s_ng = 0; s_nt = 0; }

    u32 P = 0u;
    int Kc = KTOP;
    for (int p = 0; p < 3; p++) {
        int shift = 24 - 8 * p;
        for (int t = tid; t < 8192; t += 1024) whist[t] = 0u;
        __syncthreads();
        for (int it = 0; it < nIter; it++) {
            int i = it * 1024 + tid;
            bool inr = (i < NPTS);
            u32 u = inr ? ord[i] : 0u;
            bool part = inr && ((p == 0) || ((u >> (shift + 8)) == P));
            whist_add(whist, part, (u >> shift) & 255u, lane, wid);
        }
        __syncthreads();
        sel8(whist, swarp, Kc, &s_sel, &s_krem);
        P = (P << 8) | s_sel;
        Kc = s_krem;
    }
    u32 T24 = P;
    int krem = Kc;

    // collect: warp-aggregated appends (uniform trips)
    for (int it = 0; it < nIter; it++) {
        int i = it * 1024 + tid;
        bool inr = (i < NPTS);
        u32 u = inr ? ord[i] : 0u;
        u32 p24 = u >> 8;
        u64 key = ((u64)u << 32) | (u32)(~i);
        wagg_append(sbig, 1024, &s_ng, inr && (p24 > T24), key, lane);
        wagg_append(stie, 256,  &s_nt, inr && (p24 == T24), key, lane);
    }
    __syncthreads();
    int ng = min(s_ng, 1024), nt = min(s_nt, 256);
    int take = min(krem, nt);
    for (int t = tid; t < 256; t += 1024) if (t >= nt) stie[t] = 0ULL;
    bitonic_desc(stie, 256);
    for (int t = tid; t < 1024; t += 1024) {
        u64 v = 0ULL;
        if (t < ng) v = sbig[t];
        else if (t < ng + take) v = stie[t - ng];
        sfin[t] = v;
    }
    bitonic_desc(sfin, 1024);

    // handoff to registers, then overlay smem with NmsSh
    u64 mykey = 0ULL;
    bool myvalid = false;
    float4 my = make_float4(0.f, 0.f, 0.f, 0.f);
    if (tid < KTOP) {
        mykey = sfin[tid];
        d_k1[row * KTOP + tid] = mykey;
        u32 hi = (u32)(mykey >> 32);
        float s = ord2f(hi);
        myvalid = (s >= 0.05f);
        u32 idx = ~(u32)mykey;
        if (!myvalid || idx >= NPTS) idx = 0;
        float4 bb = boxes[(size_t)b * NPTS + idx];
        my = make_float4(bb.y - 0.5f * bb.w, bb.x - 0.5f * bb.z,
                         bb.y + 0.5f * bb.w, bb.x + 0.5f * bb.z);
    }
    __syncthreads();
    float myarea = (my.z - my.x) * (my.w - my.y);
    ns->box[tid] = my;
    ns->area[tid] = myarea;
    __syncthreads();

    bool kept = nms_greedy(ns, my, myarea, myvalid, 0.4f, tid);

    if (tid < KTOP) {
        u32 hi = kept ? (u32)(mykey >> 32) : ORD_NEG1;
        u32 flat = (u32)(c * KTOP + tid);
        d_k2[b * NFLAT + flat] = ((u64)hi << 32) | (u32)(~flat);
    }
}

// ---------------- K3: fused stage-2 select (7x8-bit) + NMS + output ----------
__global__ void __launch_bounds__(1024) k_s2(const float4* __restrict__ boxes,
                                             float* __restrict__ out) {
    extern __shared__ char sm[];
    u32* whist = (u32*)(sm + OFF_WHIST);
    u64* sbig  = (u64*)(sm + OFF_BIG);
    u64* stie  = (u64*)(sm + OFF_TIE);
    u64* sfin  = (u64*)(sm + OFF_FIN);
    NmsSh* ns  = (NmsSh*)sm;
    __shared__ u32 swarp[32];
    __shared__ int swarp2[32];
    __shared__ u32 s_sel;
    __shared__ int s_krem, s_ng, s_nt;

    int b = blockIdx.x, tid = threadIdx.x, lane = tid & 31, wid = tid >> 5;
    const u64* keys = d_k2 + b * NFLAT;
    if (tid == 0) { s_ng = 0; s_nt = 0; }

    const int nIt2 = (NFLAT + 1023) / 1024;
    u64 prefix = 0ULL;
    int Kc = KTOP;
    for (int p = 0; p < 7; p++) {
        int shift = 56 - 8 * p;
        for (int t = tid; t < 8192; t += 1024) whist[t] = 0u;
        __syncthreads();
        for (int it = 0; it < nIt2; it++) {
            int f = it * 1024 + tid;
            bool inr = (f < NFLAT);
            u64 k = inr ? keys[f] : 0ULL;
            bool part = inr && ((p == 0) || ((k >> (shift + 8)) == prefix));
            whist_add(whist, part, (u32)((k >> shift) & 255ULL), lane, wid);
        }
        __syncthreads();
        sel8(whist, swarp, Kc, &s_sel, &s_krem);
        prefix = (prefix << 8) | (u64)s_sel;
        Kc = s_krem;
    }

    for (int it = 0; it < nIt2; it++) {
        int f = it * 1024 + tid;
        bool inr = (f < NFLAT);
        u64 k = inr ? keys[f] : 0ULL;
        u64 p56 = k >> 8;
        wagg_append(sbig, 1024, &s_ng, inr && (p56 > prefix), k, lane);
        wagg_append(stie, 256,  &s_nt, inr && (p56 == prefix), k, lane);
    }
    __syncthreads();
    int ng = min(s_ng, 1024), nt = min(s_nt, 256);
    int take = min(Kc, nt);
    for (int t = tid; t < 256; t += 1024) if (t >= nt) stie[t] = 0ULL;
    bitonic_desc(stie, 256);
    for (int t = tid; t < 1024; t += 1024) {
        u64 vv = 0ULL;
        if (t < ng) vv = sbig[t];
        else if (t < ng + take) vv = stie[t - ng];
        sfin[t] = vv;
    }
    bitonic_desc(sfin, 1024);

    // handoff to registers
    u64 mykey = 0ULL;
    bool myvalid = false;
    float4 my = make_float4(0.f, 0.f, 0.f, 0.f);
    float4 myraw = make_float4(0.f, 0.f, 0.f, 0.f);
    if (tid < KTOP) {
        mykey = sfin[tid];
        u32 hi = (u32)(mykey >> 32);
        float s = ord2f(hi);
        myvalid = (s >= 0.05f);
        u32 flat = ~(u32)mykey;
        u32 orig = 0;
        if (myvalid && flat < NFLAT) {
            int cc2 = (int)(flat / KTOP);
            u32 kk = flat % KTOP;
            orig = ~(u32)d_k1[(b * NCLS + cc2) * KTOP + kk];
            if (orig >= NPTS) orig = 0;
        } else myvalid = false;
        float4 bb = boxes[(size_t)b * NPTS + orig];
        myraw = bb;
        my = make_float4(bb.y - 0.5f * bb.w, bb.x - 0.5f * bb.z,
                         bb.y + 0.5f * bb.w, bb.x + 0.5f * bb.z);
    }
    __syncthreads();
    float myarea = (my.z - my.x) * (my.w - my.y);
    ns->box[tid] = my;
    ns->area[tid] = myarea;
    __syncthreads();

    bool kept = nms_greedy(ns, my, myarea, myvalid, 0.65f, tid);

    // stable compaction (= argsort(!keep)) via 2-barrier warp scan
    int flag = kept ? 1 : 0;
    int v = flag;
    #pragma unroll
    for (int off = 1; off < 32; off <<= 1) {
        int n = __shfl_up_sync(0xFFFFFFFFu, v, off);
        if (lane >= off) v += n;
    }
    if (lane == 31) swarp2[wid] = v;
    __syncthreads();
    if (tid < 32) {
        int w = swarp2[tid];
        #pragma unroll
        for (int off = 1; off < 32; off <<= 1) {
            int n = __shfl_up_sync(0xFFFFFFFFu, w, off);
            if (lane >= off) w += n;
        }
        swarp2[tid] = w;
    }
    __syncthreads();
    int incl = v + (wid ? swarp2[wid - 1] : 0);
    int total = swarp2[31];

    if (flag) {
        int m = incl - 1;
        float conf = ord2f((u32)(mykey >> 32));
        u32 flat = ~(u32)mykey;
        int cls = (int)(flat / KTOP);
        float* o = out + ((size_t)b * KTOP + m) * 6;
        o[0] = myraw.x; o[1] = myraw.y; o[2] = myraw.z; o[3] = myraw.w;
        o[4] = (float)cls; o[5] = conf;
    }
    for (int m = total + tid; m < KTOP; m += 1024) {
        float* o = out + ((size_t)b * KTOP + m) * 6;
        #pragma unroll
        for (int q = 0; q < 6; ++q) o[q] = 0.f;
    }
}

// ---------------- launch ------------------------------------------------------
extern "C" void kernel_launch(void* const* d_in, const int* in_sizes, int n_in,
                              void* d_out, int out_size) {
    const float*  cls   = (const float*)d_in[0];
    const float4* boxes = (const float4*)d_in[1];
    float* out = (float*)d_out;

    // SMEM_SZ > 48KB default cap: opt in explicitly (proven capture-safe R2-R5)
    cudaFuncSetAttribute(k_s1, cudaFuncAttributeMaxDynamicSharedMemorySize, SMEM_SZ);
    cudaFuncSetAttribute(k_s2, cudaFuncAttributeMaxDynamicSharedMemorySize, SMEM_SZ);

    k_nop<<<1, 32>>>();
    k_transpose<<<dim3((NPTS + TI - 1) / TI, BATCH), 512>>>(cls);
    k_s1<<<NROWS, 1024, SMEM_SZ>>>(boxes);
    k_s2<<<BATCH, 1024, SMEM_SZ>>>(boxes, out);
}

// round 13
// speedup vs baseline: 1.8978x; 1.8978x over previous
#include <cuda_runtime.h>

typedef unsigned int u32;
typedef unsigned long long u64;

#define BATCH  8
#define NPTS   100000
#define NCLS   10
#define KTOP   1000
#define NROWS  (BATCH * NCLS)      // 80
#define NFLAT  (NCLS * KTOP)       // 10000
#define NW     16                  // u64 words covering 1024 bits
#define NPAD   1024                // padded rows for the scan smem
#define ORD_NEG1 0x407FFFFFu       // f2ord(-1.0f)
#define TI     512
#define SCAN_SMEM (NPAD * NW * 8)  // 131072 bytes

// ---------------- static device scratch -------------------------------------
__device__ u32    d_ord  [NROWS * NPTS];      // 32 MB ordered score bits
__device__ u64    d_k1   [NROWS * KTOP];
__device__ float4 d_corn1[NROWS * KTOP];
__device__ u64    d_k2   [BATCH * NFLAT];
__device__ u64    d_k2s  [BATCH * KTOP];
__device__ u64    d_val2 [BATCH * NW];
__device__ float4 d_corn2[BATCH * KTOP];
__device__ float4 d_raw2 [BATCH * KTOP];
__device__ u64    d_mask2[BATCH * KTOP * NW]; // 1 MB

// ---------------- helpers ----------------------------------------------------
__device__ __forceinline__ u32 f2ord(float f) {
    u32 b = __float_as_uint(f);
    return b ^ ((b & 0x80000000u) ? 0xFFFFFFFFu : 0x80000000u);
}
__device__ __forceinline__ float ord2f(u32 u) {
    u32 b = u ^ ((u & 0x80000000u) ? 0x80000000u : 0xFFFFFFFFu);
    return __uint_as_float(b);
}

__device__ void bitonic_desc(u64* s, int n) {
    for (int k = 2; k <= n; k <<= 1) {
        for (int j = k >> 1; j > 0; j >>= 1) {
            __syncthreads();
            for (int i = threadIdx.x; i < n; i += blockDim.x) {
                int ixj = i ^ j;
                if (ixj > i) {
                    u64 a = s[i], bb = s[ixj];
                    if ((a < bb) == ((i & k) == 0)) { s[i] = bb; s[ixj] = a; }
                }
            }
        }
    }
    __syncthreads();
}

// Warp-aggregated shared histogram add. Fully-converged warps only.
__device__ __forceinline__ void hist_add(u32* hist, bool part, u32 dgt, int lane) {
    u32 act = __ballot_sync(0xFFFFFFFFu, part);
    if (part) {
        u32 peers = __match_any_sync(act, dgt);
        if (lane == __ffs(peers) - 1)
            atomicAdd(&hist[dgt], (u32)__popc(peers));
    }
}

// Highest 12-bit bin with count(> bin) < K <= count(>= bin).  1024 threads.
__device__ void select_bin(const u32* hist, u32* swarp, int K, u32* s_sel, int* s_krem) {
    int t = threadIdx.x, lane = t & 31, wid = t >> 5;
    u32 h0 = hist[4 * t], h1 = hist[4 * t + 1], h2 = hist[4 * t + 2], h3 = hist[4 * t + 3];
    u32 mysum = h0 + h1 + h2 + h3;
    u32 v = mysum;
    #pragma unroll
    for (int off = 1; off < 32; off <<= 1) {
        u32 n = __shfl_down_sync(0xFFFFFFFFu, v, off);
        if (lane + off < 32) v += n;
    }
    if (lane == 0) swarp[wid] = v;
    __syncthreads();
    if (t < 32) {
        u32 w = swarp[t];
        #pragma unroll
        for (int off = 1; off < 32; off <<= 1) {
            u32 n = __shfl_down_sync(0xFFFFFFFFu, w, off);
            if (lane + off < 32) w += n;
        }
        swarp[t] = w;
    }
    __syncthreads();
    u32 S_incl = v + ((wid < 31) ? swarp[wid + 1] : 0u);
    u32 above = S_incl - mysum;
    if (above < (u32)K && S_incl >= (u32)K) {
        u32 cum = above;
        u32 hh[4] = { h3, h2, h1, h0 };
        int bb[4] = { 4 * t + 3, 4 * t + 2, 4 * t + 1, 4 * t };
        #pragma unroll
        for (int q = 0; q < 4; q++) {
            if (cum + hh[q] >= (u32)K) { *s_sel = (u32)bb[q]; *s_krem = K - (int)cum; break; }
            cum += hh[q];
        }
    }
    __syncthreads();
}

// ---------------- thread-owns-box blocked greedy NMS (R7, measured) ----------
struct NmsSh {
    float4 box[1024];
    float  area[1024];
    u64    mat[64];
    u32    cand[2];
    u64    alive;
};

__device__ bool nms_greedy(NmsSh* ns, float4 my, float myarea, bool myvalid,
                           float thresh, int tid) {
    bool supp = false, kept = false;
    int myblk = tid >> 6;
    int lane = tid & 31;
    for (int blk = 0; blk < 16; blk++) {
        if ((tid >> 6) == blk) {                 // warp-uniform (2 warps)
            u32 bal = __ballot_sync(0xFFFFFFFFu, myvalid && !supp);
            if (lane == 0) ns->cand[(tid >> 5) & 1] = bal;
        }
        __syncthreads();
        u64 cand = ((u64)ns->cand[1] << 32) | (u64)ns->cand[0];
        int base = blk << 6;

        {   // intra-block 64x64 (4 j's/thread, shfl-OR reduce)
            int i = tid >> 4;
            u64 bits = 0ULL;
            if ((cand >> i) & 1ULL) {
                float4 a = ns->box[base + i];
                float areaA = ns->area[base + i];
                int j0 = (tid & 15) << 2;
                #pragma unroll
                for (int q = 0; q < 4; q++) {
                    int j = j0 + q;
                    if (j > i) {
                        float4 c = ns->box[base + j];
                        float ih = fmaxf(fminf(a.z, c.z) - fmaxf(a.x, c.x), 0.0f);
                        float iw = fmaxf(fminf(a.w, c.w) - fmaxf(a.y, c.y), 0.0f);
                        float inter = ih * iw;
                        float uni = fmaxf(areaA + ns->area[base + j] - inter, 1e-8f);
                        if (inter / uni > thresh) bits |= 1ULL << j;
                    }
                }
            }
            #pragma unroll
            for (int off = 8; off; off >>= 1)
                bits |= __shfl_xor_sync(0xFFFFFFFFu, bits, off);
            if ((tid & 15) == 0) ns->mat[tid >> 4] = bits;
        }
        __syncthreads();

        if (tid == 0) {                          // serial resolve
            u64 suppB = 0ULL, aliveB = 0ULL;
            for (int q0 = 0; q0 < 64; q0 += 8) {
                u64 dw[8];
                #pragma unroll
                for (int r = 0; r < 8; r++) dw[r] = ns->mat[q0 + r];
                #pragma unroll
                for (int r = 0; r < 8; r++) {
                    int q = q0 + r;
                    if (((cand >> q) & 1ULL) && !((suppB >> q) & 1ULL)) {
                        aliveB |= 1ULL << q;
                        suppB |= dw[r];
                    }
                }
            }
            ns->alive = aliveB;
        }
        __syncthreads();
        u64 aliveM = ns->alive;

        if (myblk == blk) {
            kept = myvalid && ((aliveM >> (tid & 63)) & 1ULL);
            supp = !kept;
        } else if (myblk > blk && myvalid && !supp) {
            u64 tmp = aliveM;
            while (tmp) {
                int ii = __ffsll(tmp) - 1;
                tmp &= tmp - 1;
                float4 a = ns->box[base + ii];
                float areaA = ns->area[base + ii];
                float ih = fmaxf(fminf(a.z, my.z) - fmaxf(a.x, my.x), 0.0f);
                float iw = fmaxf(fminf(a.w, my.w) - fmaxf(a.y, my.y), 0.0f);
                float inter = ih * iw;
                float uni = fmaxf(areaA + myarea - inter, 1e-8f);
                if (inter / uni > thresh) { supp = true; break; }
            }
        }
    }
    return kept;
}

// ---------------- stage-2 bit-scan (R5, measured; NPAD rows, pad = zero) -----
__device__ void warp_scan(const u64* smask, u64 V, u64* skw) {
    int lane = threadIdx.x & 31;
    u64 rem = 0ULL;
    for (int blk = 0; blk < 16; blk++) {
        u64 Sb = __shfl_sync(0xFFFFFFFFu, rem, blk);
        u64 Vb = __shfl_sync(0xFFFFFFFFu, V, blk);
        int base = blk << 6;
        u64 aliveM = 0ULL;
        if (lane == 0) {
            for (int q0 = 0; q0 < 64; q0 += 8) {
                u64 dw[8];
                #pragma unroll
                for (int r = 0; r < 8; r++) dw[r] = smask[(base + q0 + r) * NW + blk];
                #pragma unroll
                for (int r = 0; r < 8; r++) {
                    int q = q0 + r;
                    if (((Vb >> q) & 1ULL) && !((Sb >> q) & 1ULL)) {
                        Sb |= dw[r];
                        aliveM |= 1ULL << q;
                    }
                }
            }
            skw[blk] = aliveM;
        }
        aliveM = __shfl_sync(0xFFFFFFFFu, aliveM, 0);
        int lw = lane & 15;
        #pragma unroll 8
        for (int q = 0; q < 64; q++) {
            u64 sel = (u64)0 - ((aliveM >> q) & 1ULL);
            rem |= smask[(base + q) * NW + lw] & sel;
        }
    }
}

// ---------------- K: profiling-slot shim -------------------------------------
__global__ void k_nop() {}

// ---------------- K1: mask + transpose to per-(b,c) rows --------------------
__global__ void k_transpose(const float* __restrict__ cls) {
    __shared__ u32 tile[TI * NCLS];
    int b  = blockIdx.y;
    int i0 = blockIdx.x * TI;
    int cnt = min(TI, NPTS - i0);
    const float* src = cls + ((size_t)b * NPTS + i0) * NCLS;
    for (int t = threadIdx.x; t < cnt * NCLS; t += blockDim.x) {
        float s = src[t];
        s = (s >= 0.05f) ? s : -1.0f;
        tile[t] = f2ord(s);
    }
    __syncthreads();
    for (int c = 0; c < NCLS; ++c) {
        u32* dst = d_ord + (size_t)(b * NCLS + c) * NPTS + i0;
        for (int r = threadIdx.x; r < cnt; r += blockDim.x)
            dst[r] = tile[r * NCLS + c];
    }
}

// ---------------- K2: stage-1 select (2x12-bit radix, uint4 loads) -----------
__global__ void __launch_bounds__(1024) k_sel1(const float4* __restrict__ boxes) {
    __shared__ u32 hist[4096];
    __shared__ u32 swarp[32];
    __shared__ u64 sbig[1024], stie[256], sfin[1024];
    __shared__ u32 s_sel;
    __shared__ int s_krem, s_ng, s_nt;

    int row = blockIdx.x;
    int b = row / NCLS, c = row % NCLS;
    const u32* ord = d_ord + (size_t)row * NPTS;
    const uint4* ord4 = (const uint4*)ord;
    const int N4 = NPTS / 4;                    // 25000, NPTS % 4 == 0
    const int nIt4 = (N4 + 1023) / 1024;        // 25
    int tid = threadIdx.x, lane = tid & 31;

    if (tid == 0) { s_ng = 0; s_nt = 0; }
    for (int t = tid; t < 4096; t += 1024) hist[t] = 0u;
    __syncthreads();

    // pass A: digit = bits 31..20 (vectorized, uniform trips)
    for (int it = 0; it < nIt4; it++) {
        int i4 = it * 1024 + tid;
        bool inr = (i4 < N4);
        uint4 u = inr ? ord4[i4] : make_uint4(0u, 0u, 0u, 0u);
        hist_add(hist, inr, u.x >> 20, lane);
        hist_add(hist, inr, u.y >> 20, lane);
        hist_add(hist, inr, u.z >> 20, lane);
        hist_add(hist, inr, u.w >> 20, lane);
    }
    __syncthreads();
    select_bin(hist, swarp, KTOP, &s_sel, &s_krem);
    u32 D1 = s_sel;
    int K2v = s_krem;

    // pass B: digit = bits 19..8 among prefix matches
    for (int t = tid; t < 4096; t += 1024) hist[t] = 0u;
    __syncthreads();
    for (int it = 0; it < nIt4; it++) {
        int i4 = it * 1024 + tid;
        bool inr = (i4 < N4);
        uint4 u = inr ? ord4[i4] : make_uint4(0u, 0u, 0u, 0u);
        hist_add(hist, inr && ((u.x >> 20) == D1), (u.x >> 8) & 4095u, lane);
        hist_add(hist, inr && ((u.y >> 20) == D1), (u.y >> 8) & 4095u, lane);
        hist_add(hist, inr && ((u.z >> 20) == D1), (u.z >> 8) & 4095u, lane);
        hist_add(hist, inr && ((u.w >> 20) == D1), (u.w >> 8) & 4095u, lane);
    }
    __syncthreads();
    select_bin(hist, swarp, K2v, &s_sel, &s_krem);
    u32 T24 = (D1 << 12) | s_sel;
    int krem = s_krem;

    // collect (vectorized; plain atomics, no collectives)
    for (int i4 = tid; i4 < N4; i4 += 1024) {
        uint4 u = ord4[i4];
        u32 uv[4] = { u.x, u.y, u.z, u.w };
        #pragma unroll
        for (int q = 0; q < 4; q++) {
            u32 uu = uv[q];
            u32 p24 = uu >> 8;
            int i = i4 * 4 + q;
            if (p24 > T24) {
                int pos = atomicAdd(&s_ng, 1);
                if (pos < 1024) sbig[pos] = ((u64)uu << 32) | (u32)(~i);
            } else if (p24 == T24) {
                int pos = atomicAdd(&s_nt, 1);
                if (pos < 256) stie[pos] = ((u64)uu << 32) | (u32)(~i);
            }
        }
    }
    __syncthreads();
    int ng = min(s_ng, 1024), nt = min(s_nt, 256);
    int take = min(krem, nt);
    for (int t = tid; t < 256; t += 1024) if (t >= nt) stie[t] = 0ULL;
    bitonic_desc(stie, 256);
    for (int t = tid; t < 1024; t += 1024) {
        u64 v = 0ULL;
        if (t < ng) v = sbig[t];
        else if (t < ng + take) v = stie[t - ng];
        sfin[t] = v;
    }
    bitonic_desc(sfin, 1024);

    if (tid < KTOP) {
        u64 key = sfin[tid];
        d_k1[row * KTOP + tid] = key;
        u32 hi = (u32)(key >> 32);
        float s = ord2f(hi);
        bool valid = (s >= 0.05f);
        u32 idx = ~(u32)key;
        if (!valid || idx >= NPTS) idx = 0;
        float4 bb = boxes[(size_t)b * NPTS + idx];
        d_corn1[row * KTOP + tid] = make_float4(bb.y - 0.5f * bb.w, bb.x - 0.5f * bb.z,
                                                bb.y + 0.5f * bb.w, bb.x + 0.5f * bb.z);
    }
}

// ---------------- K3: stage-1 NMS + stage-2 key emission (R7) ----------------
__global__ void __launch_bounds__(1024) k_nms1() {
    __shared__ NmsSh ns;
    int row = blockIdx.x, tid = threadIdx.x;
    int b = row / NCLS, c = row % NCLS;
    u64 mykey = 0ULL;
    bool myvalid = false;
    float4 my = make_float4(0.f, 0.f, 0.f, 0.f);
    if (tid < KTOP) {
        mykey = d_k1[row * KTOP + tid];
        myvalid = ord2f((u32)(mykey >> 32)) >= 0.05f;
        my = d_corn1[(size_t)row * KTOP + tid];
    }
    float myarea = (my.z - my.x) * (my.w - my.y);
    ns.box[tid] = my;
    ns.area[tid] = myarea;
    __syncthreads();

    bool kept = nms_greedy(&ns, my, myarea, myvalid, 0.4f, tid);

    if (tid < KTOP) {
        u32 hi = kept ? (u32)(mykey >> 32) : ORD_NEG1;
        u32 flat = (u32)(c * KTOP + tid);
        d_k2[b * NFLAT + flat] = ((u64)hi << 32) | (u32)(~flat);
    }
}

// ---------------- K4: stage-2 select (5x12-bit radix, R7) + gather -----------
__global__ void __launch_bounds__(1024) k_sel2(const float4* __restrict__ boxes) {
    __shared__ u32 hist[4096];
    __shared__ u32 swarp[32];
    __shared__ u64 sbig[1024], stie[256], sfin[1024];
    __shared__ u64 sval[16];
    __shared__ u32 s_sel;
    __shared__ int s_krem, s_ng, s_nt;

    int b = blockIdx.x, tid = threadIdx.x, lane = tid & 31;
    const u64* keys = d_k2 + b * NFLAT;
    if (tid == 0) { s_ng = 0; s_nt = 0; }
    if (tid < 16) sval[tid] = 0ULL;

    const int nIt2 = (NFLAT + 1023) / 1024;
    u64 prefix = 0ULL;
    int Kc = KTOP;
    for (int p = 0; p < 5; p++) {
        int shift = 52 - 12 * p;
        for (int t = tid; t < 4096; t += 1024) hist[t] = 0u;
        __syncthreads();
        for (int it = 0; it < nIt2; it++) {
            int f = it * 1024 + tid;
            bool inr = (f < NFLAT);
            u64 k = inr ? keys[f] : 0ULL;
            bool part = inr && ((p == 0) || ((k >> (shift + 12)) == prefix));
            hist_add(hist, part, (u32)((k >> shift) & 4095ULL), lane);
        }
        __syncthreads();
        select_bin(hist, swarp, Kc, &s_sel, &s_krem);
        prefix = (prefix << 12) | (u64)s_sel;
        Kc = s_krem;
    }

    for (int f = tid; f < NFLAT; f += 1024) {
        u64 k = keys[f];
        u64 p60 = k >> 4;
        if (p60 > prefix) {
            int pos = atomicAdd(&s_ng, 1);
            if (pos < 1024) sbig[pos] = k;
        } else if (p60 == prefix) {
            int pos = atomicAdd(&s_nt, 1);
            if (pos < 256) stie[pos] = k;
        }
    }
    __syncthreads();
    int ng = min(s_ng, 1024), nt = min(s_nt, 256);
    int take = min(Kc, nt);
    for (int t = tid; t < 256; t += 1024) if (t >= nt) stie[t] = 0ULL;
    bitonic_desc(stie, 256);
    for (int t = tid; t < 1024; t += 1024) {
        u64 vv = 0ULL;
        if (t < ng) vv = sbig[t];
        else if (t < ng + take) vv = stie[t - ng];
        sfin[t] = vv;
    }
    bitonic_desc(sfin, 1024);

    if (tid < KTOP) {
        u64 key = sfin[tid];
        d_k2s[b * KTOP + tid] = key;
        u32 hi = (u32)(key >> 32);
        float s = ord2f(hi);
        bool valid = (s >= 0.05f);
        u32 flat = ~(u32)key;
        u32 orig = 0;
        if (valid && flat < NFLAT) {
            int cc2 = (int)(flat / KTOP);
            u32 kk = flat % KTOP;
            orig = ~(u32)d_k1[(b * NCLS + cc2) * KTOP + kk];
            if (orig >= NPTS) orig = 0;
        } else valid = false;
        float4 bb = boxes[(size_t)b * NPTS + orig];
        d_raw2[b * KTOP + tid] = bb;
        d_corn2[b * KTOP + tid] = make_float4(bb.y - 0.5f * bb.w, bb.x - 0.5f * bb.z,
                                              bb.y + 0.5f * bb.w, bb.x + 0.5f * bb.z);
        if (valid) atomicOr(&sval[tid >> 6], 1ULL << (tid & 63));
    }
    __syncthreads();
    if (tid < 16) d_val2[b * NW + tid] = sval[tid];
}

// ---------------- K5: stage-2 full-chip mask build ---------------------------
__global__ void __launch_bounds__(256) k_mask2() {
    __shared__ float4 scor[KTOP];
    int row = blockIdx.y;
    const float4* cr = d_corn2 + (size_t)row * KTOP;
    for (int t = threadIdx.x; t < KTOP; t += blockDim.x) scor[t] = cr[t];
    __syncthreads();
    int chunk = (KTOP * NW) / gridDim.x;       // gridDim.x = 16 -> 1000
    int t0 = blockIdx.x * chunk;
    for (int t = t0 + threadIdx.x; t < t0 + chunk; t += blockDim.x) {
        int i = t >> 4, w = t & 15;
        u64 m = 0ULL;
        int jbase = w << 6;
        int j0 = max(jbase, i + 1);
        int j1 = min(jbase + 64, KTOP);
        if (j0 < j1) {
            float4 a = scor[i];
            float areaA = (a.z - a.x) * (a.w - a.y);
            for (int j = j0; j < j1; ++j) {
                float4 cc = scor[j];
                float ih = fmaxf(fminf(a.z, cc.z) - fmaxf(a.x, cc.x), 0.0f);
                float iw = fmaxf(fminf(a.w, cc.w) - fmaxf(a.y, cc.y), 0.0f);
                float inter = ih * iw;
                float areaB = (cc.z - cc.x) * (cc.w - cc.y);
                float iou = inter / fmaxf(areaA + areaB - inter, 1e-8f);
                if (iou > 0.65f) m |= 1ULL << (j - jbase);
            }
        }
        d_mask2[(size_t)row * KTOP * NW + t] = m;
    }
}

// ---------------- K6: stage-2 scan + compaction + output ---------------------
__global__ void __launch_bounds__(1024) k_out(float* __restrict__ out) {
    extern __shared__ u64 smask[];             // NPAD*NW words
    __shared__ u64 skw[16];
    __shared__ int swarp2[32];
    int b = blockIdx.x, tid = threadIdx.x;
    int lane = tid & 31, wid = tid >> 5;

    const u64* mg = d_mask2 + (size_t)b * KTOP * NW;
    for (int t = tid; t < KTOP * NW; t += 1024) smask[t] = mg[t];
    for (int t = KTOP * NW + tid; t < NPAD * NW; t += 1024) smask[t] = 0ULL;
    __syncthreads();
    if (tid < 32) {
        u64 V = (tid < 16) ? d_val2[b * NW + tid] : 0ULL;
        warp_scan(smask, V, skw);
    }
    __syncthreads();

    bool kept = false;
    u64 mykey = 0ULL;
    if (tid < KTOP) {
        kept = (skw[tid >> 6] >> (tid & 63)) & 1ULL;
        mykey = d_k2s[b * KTOP + tid];
    }

    int flag = kept ? 1 : 0;
    int v = flag;
    #pragma unroll
    for (int off = 1; off < 32; off <<= 1) {
        int n = __shfl_up_sync(0xFFFFFFFFu, v, off);
        if (lane >= off) v += n;
    }
    if (lane == 31) swarp2[wid] = v;
    __syncthreads();
    if (tid < 32) {
        int w = swarp2[tid];
        #pragma unroll
        for (int off = 1; off < 32; off <<= 1) {
            int n = __shfl_up_sync(0xFFFFFFFFu, w, off);
            if (lane >= off) w += n;
        }
        swarp2[tid] = w;
    }
    __syncthreads();
    int incl = v + (wid ? swarp2[wid - 1] : 0);
    int total = swarp2[31];

    if (flag) {
        int m = incl - 1;
        float conf = ord2f((u32)(mykey >> 32));
        u32 flat = ~(u32)mykey;
        int cls = (int)(flat / KTOP);
        float4 raw = d_raw2[b * KTOP + tid];
        float* o = out + ((size_t)b * KTOP + m) * 6;
        o[0] = raw.x; o[1] = raw.y; o[2] = raw.z; o[3] = raw.w;
        o[4] = (float)cls; o[5] = conf;
    }
    for (int m = total + tid; m < KTOP; m += 1024) {
        float* o = out + ((size_t)b * KTOP + m) * 6;
        #pragma unroll
        for (int q = 0; q < 6; ++q) o[q] = 0.f;
    }
}

// ---------------- launch ------------------------------------------------------
extern "C" void kernel_launch(void* const* d_in, const int* in_sizes, int n_in,
                              void* d_out, int out_size) {
    const float*  cls   = (const float*)d_in[0];
    const float4* boxes = (const float4*)d_in[1];
    float* out = (float*)d_out;

    cudaFuncSetAttribute(k_out, cudaFuncAttributeMaxDynamicSharedMemorySize, SCAN_SMEM);

    k_nop<<<1, 32>>>();                                  // idx 0
    k_nop<<<1, 32>>>();                                  // idx 1
    k_transpose<<<dim3((NPTS + TI - 1) / TI, BATCH), 512>>>(cls);  // idx 2
    k_sel1<<<NROWS, 1024>>>(boxes);                      // idx 3 (ncu slot)
    k_nms1<<<NROWS, 1024>>>();
    k_sel2<<<BATCH, 1024>>>(boxes);
    k_mask2<<<dim3(16, BATCH), 256>>>();
    k_out<<<BATCH, 1024, SCAN_SMEM>>>(out);
}